// round 8
// baseline (speedup 1.0000x reference)
#include <cuda_runtime.h>
#include <cuda_fp16.h>
#include <math.h>

// RenderNet volume rendering — round 8: fp16 weight buffer (byte cut).
// Shapes: B=1, C=32, Z=64, N=65536.
// K1: thread-per-ray weights, chunked prefetch (MLP 16); wsum/acc in fp32;
//     weights stored fp16 to g_wbuf (8MB -> halves intermediate traffic,
//     stays L2-resident under K2's feat stream).
// K2: single-wave static composite (740x256, 5 CTA/SM); warp = 4 channels x
//     8 ray-quads; weights = one 64B line/warp/z (L2 hit), feat LDG.128 .cs.
// out: [0]=loss, [1..1+CN)=rgb_e, [1+CN..1+2CN)=feat_e, [..+N)=acc_e
// (out+1 only 4B-aligned -> scalar output stores).

#define RN_C 32
#define RN_Z 64
#define RN_N 65536
#define RAW_NOISE_STD 0.1f
#define FAR_DIST 1e10f

#define K2_GRID 740
#define K2_THREADS 256
#define K2_NWARPS (K2_GRID * K2_THREADS / 32)       // 5920
#define K2_WARPJOBS ((RN_C / 4) * (RN_N / 4 / 8))   // 16384

__device__ __half g_wbuf[RN_Z * RN_N];   // weights [z][n], fp16, 8MB

// ---------------- K1: weights, chunked prefetch ----------------
__global__ void __launch_bounds__(64)
rn_weights(const float* __restrict__ occ,
           const float* __restrict__ z_dist,
           const float* __restrict__ noise,
           float* __restrict__ out)
{
    __shared__ float s_dist[RN_Z];
    const int tid = threadIdx.x;
    s_dist[tid] = (tid < RN_Z - 1) ? (z_dist[tid + 1] - z_dist[tid]) : FAR_DIST;
    __syncthreads();

    const int n = blockIdx.x * 64 + tid;
    const float4* np4 = (const float4*)(noise + (size_t)n * RN_Z);
    const float*  occp = occ + n;

    float trans = 1.0f;
    float wsum  = 0.0f;

#pragma unroll
    for (int zc = 0; zc < RN_Z / 16; ++zc) {        // 4 chunks of 16 z
        float ov[16];
#pragma unroll
        for (int j = 0; j < 16; ++j)
            ov[j] = __ldcs(occp + (size_t)(zc * 16 + j) * RN_N);
        float4 nq[4];
#pragma unroll
        for (int j = 0; j < 4; ++j)
            nq[j] = __ldcs(np4 + zc * 4 + j);
        float nv[16];
#pragma unroll
        for (int j = 0; j < 4; ++j) {
            nv[j * 4 + 0] = nq[j].x; nv[j * 4 + 1] = nq[j].y;
            nv[j * 4 + 2] = nq[j].z; nv[j * 4 + 3] = nq[j].w;
        }
#pragma unroll
        for (int j = 0; j < 16; ++j) {
            int z = zc * 16 + j;
            float raw = fmaxf(fmaf(nv[j], RAW_NOISE_STD, ov[j]), 0.0f);
            float alpha = 1.0f - expf(-raw * s_dist[z]);
            float w = alpha * trans;
            trans *= (1.0f - alpha + 1e-10f);
            wsum  += w;                                  // fp32 accumulation
            g_wbuf[(size_t)z * RN_N + n] = __float2half_rn(w);
        }
    }

    float* am = out + 1 + 2 * (size_t)RN_C * RN_N;
    am[n] = fminf(fmaxf(wsum, 0.0f), 1.0f);
    if (n == 0) out[0] = 0.0f;
}

// ---------------- K2: composite, warp-shared fp16 weights ----------------
__global__ void __launch_bounds__(K2_THREADS, 5)
rn_composite(const float* __restrict__ feat,
             float* __restrict__ out)
{
    const int wid0 = (blockIdx.x * K2_THREADS + threadIdx.x) >> 5;
    const int lane = threadIdx.x & 31;
    const int c2   = lane >> 3;     // 0..3 channel within group
    const int q8   = lane & 7;      // 0..7 quad within group

    float* rgb = out + 1;
    float* fe  = out + 1 + (size_t)RN_C * RN_N;
    const size_t ZN = (size_t)RN_Z * (size_t)RN_N;

    for (int wj = wid0; wj < K2_WARPJOBS; wj += K2_NWARPS) {
        const int cg = wj >> 11;               // 0..7 channel group
        const int qg = wj & 2047;              // 0..2047 quad group
        const int c  = cg * 4 + c2;            // channel 0..31
        const int n0 = (qg * 8 + q8) * 4;      // ray start

        const float*  fp = feat + (size_t)c * ZN + n0;
        const __half* wp = g_wbuf + n0;

        float4 a = {0.f, 0.f, 0.f, 0.f};
#pragma unroll 4
        for (int z = 0; z < RN_Z; ++z) {
            // 4 fp16 weights = 8B per lane, one 64B line per warp (L2 hit)
            uint2 wraw = __ldg((const uint2*)(wp + (size_t)z * RN_N));
            const __half2* wh = (const __half2*)&wraw;
            float2 w01 = __half22float2(wh[0]);
            float2 w23 = __half22float2(wh[1]);
            float4 v = __ldcs((const float4*)(fp + (size_t)z * RN_N));
            a.x = fmaf(w01.x, v.x, a.x);
            a.y = fmaf(w01.y, v.y, a.y);
            a.z = fmaf(w23.x, v.z, a.z);
            a.w = fmaf(w23.y, v.w, a.w);
        }

        const size_t o0 = (size_t)c * RN_N + n0;
        float av[4] = {a.x, a.y, a.z, a.w};
#pragma unroll
        for (int j = 0; j < 4; ++j) {
            fe[o0 + j]  = av[j];
            rgb[o0 + j] = 1.0f / (1.0f + expf(-av[j])) - 0.5f;
        }
    }
}

// ---------------- generic fallback (any Z/N) ----------------
__global__ void __launch_bounds__(256)
rendernet_generic(const float* __restrict__ feat,
                  const float* __restrict__ occ,
                  const float* __restrict__ z_dist,
                  const float* __restrict__ noise,
                  float* __restrict__ out,
                  int Z, int N)
{
    extern __shared__ float s_d[];
    int tid = threadIdx.x;
    if (tid < Z)
        s_d[tid] = (tid < Z - 1) ? (z_dist[tid + 1] - z_dist[tid]) : FAR_DIST;
    __syncthreads();

    int n = blockIdx.x * blockDim.x + tid;
    if (n >= N) return;

    float acc[RN_C];
#pragma unroll
    for (int c = 0; c < RN_C; ++c) acc[c] = 0.0f;

    const float* occp   = occ + n;
    const float* noisep = noise + (size_t)n * Z;
    const float* featp  = feat + n;
    const size_t ZN = (size_t)Z * (size_t)N;

    float trans = 1.0f, wsum = 0.0f;
    for (int z = 0; z < Z; ++z) {
        float raw = fmaxf(fmaf(noisep[z], RAW_NOISE_STD, occp[(size_t)z * N]), 0.0f);
        float alpha = 1.0f - expf(-raw * s_d[z]);
        float w = alpha * trans;
        trans *= (1.0f - alpha + 1e-10f);
        wsum += w;
        const float* fz = featp + (size_t)z * N;
#pragma unroll
        for (int c = 0; c < RN_C; ++c)
            acc[c] = fmaf(w, fz[(size_t)c * ZN], acc[c]);
    }
    float* rgb = out + 1;
    float* fe  = out + 1 + (size_t)RN_C * N;
    float* am  = out + 1 + 2 * (size_t)RN_C * N;
#pragma unroll
    for (int c = 0; c < RN_C; ++c) {
        float f = acc[c];
        fe[(size_t)c * N + n]  = f;
        rgb[(size_t)c * N + n] = 1.0f / (1.0f + expf(-f)) - 0.5f;
    }
    am[n] = fminf(fmaxf(wsum, 0.0f), 1.0f);
    if (n == 0) out[0] = 0.0f;
}

extern "C" void kernel_launch(void* const* d_in, const int* in_sizes, int n_in,
                              void* d_out, int out_size)
{
    const float* feat   = (const float*)d_in[0];
    const float* occ    = (const float*)d_in[1];
    const float* z_dist = (const float*)d_in[2];
    const float* noise  = (const float*)d_in[3];
    float* out = (float*)d_out;

    int Z = in_sizes[2];
    int N = in_sizes[1] / Z;

    if (Z == RN_Z && N == RN_N) {
        rn_weights<<<RN_N / 64, 64>>>(occ, z_dist, noise, out);
        rn_composite<<<K2_GRID, K2_THREADS>>>(feat, out);
    } else {
        int block = 256;
        int grid = (N + block - 1) / block;
        rendernet_generic<<<grid, block, Z * sizeof(float)>>>(feat, occ, z_dist, noise, out, Z, N);
    }
}

// round 9
// speedup vs baseline: 1.0110x; 1.0110x over previous
#include <cuda_runtime.h>
#include <cuda_fp16.h>
#include <math.h>

// RenderNet volume rendering — round 9: fp16 wbuf kept; K1 stores fixed.
// Shapes: B=1, C=32, Z=64, N=65536.
// K1: 2 rays/thread, chunked prefetch (16 z per chunk). occ read as float2,
//     weights stored packed __half2 (STG.32) -> no narrow stores. Grid 512x64.
// K2: single-wave static composite (740x256, 5 CTA/SM); warp = 4 channels x
//     8 ray-quads; fp16 weights = one 64B line/warp/z (L2 hit), feat LDG.128.
// out: [0]=loss, [1..1+CN)=rgb_e, [1+CN..1+2CN)=feat_e, [..+N)=acc_e
// (out+1 only 4B-aligned -> scalar output stores).

#define RN_C 32
#define RN_Z 64
#define RN_N 65536
#define RAW_NOISE_STD 0.1f
#define FAR_DIST 1e10f

#define K2_GRID 740
#define K2_THREADS 256
#define K2_NWARPS (K2_GRID * K2_THREADS / 32)       // 5920
#define K2_WARPJOBS ((RN_C / 4) * (RN_N / 4 / 8))   // 16384

__device__ __half g_wbuf[RN_Z * RN_N];   // weights [z][n], fp16, 8MB

// ---------------- K1: weights, 2 rays/thread, chunked prefetch ----------------
__global__ void __launch_bounds__(64)
rn_weights(const float* __restrict__ occ,
           const float* __restrict__ z_dist,
           const float* __restrict__ noise,
           float* __restrict__ out)
{
    __shared__ float s_dist[RN_Z];
    const int tid = threadIdx.x;
    s_dist[tid] = (tid < RN_Z - 1) ? (z_dist[tid + 1] - z_dist[tid]) : FAR_DIST;
    __syncthreads();

    const int n0 = (blockIdx.x * 64 + tid) * 2;    // ray pair {n0, n0+1}
    const float4* npa = (const float4*)(noise + (size_t)n0 * RN_Z);
    const float4* npb = (const float4*)(noise + (size_t)(n0 + 1) * RN_Z);

    float transA = 1.0f, wsumA = 0.0f;
    float transB = 1.0f, wsumB = 0.0f;

#pragma unroll
    for (int zc = 0; zc < RN_Z / 16; ++zc) {        // 4 chunks of 16 z
        // ---- batch-load: 16 float2 occ + 2x4 float4 noise (independent) ----
        float2 ov[16];
#pragma unroll
        for (int j = 0; j < 16; ++j)
            ov[j] = __ldcs((const float2*)(occ + (size_t)(zc * 16 + j) * RN_N + n0));
        float4 nqa[4], nqb[4];
#pragma unroll
        for (int j = 0; j < 4; ++j) {
            nqa[j] = __ldcs(npa + zc * 4 + j);
            nqb[j] = __ldcs(npb + zc * 4 + j);
        }
        float nva[16], nvb[16];
#pragma unroll
        for (int j = 0; j < 4; ++j) {
            nva[j*4+0] = nqa[j].x; nva[j*4+1] = nqa[j].y;
            nva[j*4+2] = nqa[j].z; nva[j*4+3] = nqa[j].w;
            nvb[j*4+0] = nqb[j].x; nvb[j*4+1] = nqb[j].y;
            nvb[j*4+2] = nqb[j].z; nvb[j*4+3] = nqb[j].w;
        }
        // ---- 16 steps of the two interleaved recurrences ----
#pragma unroll
        for (int j = 0; j < 16; ++j) {
            int z = zc * 16 + j;
            float d = s_dist[z];

            float rawA = fmaxf(fmaf(nva[j], RAW_NOISE_STD, ov[j].x), 0.0f);
            float rawB = fmaxf(fmaf(nvb[j], RAW_NOISE_STD, ov[j].y), 0.0f);
            float aA = 1.0f - expf(-rawA * d);
            float aB = 1.0f - expf(-rawB * d);
            float wA = aA * transA;
            float wB = aB * transB;
            transA *= (1.0f - aA + 1e-10f);
            transB *= (1.0f - aB + 1e-10f);
            wsumA += wA;
            wsumB += wB;

            *(__half2*)&g_wbuf[(size_t)z * RN_N + n0] =
                __floats2half2_rn(wA, wB);          // packed STG.32
        }
    }

    float* am = out + 1 + 2 * (size_t)RN_C * RN_N;
    am[n0]     = fminf(fmaxf(wsumA, 0.0f), 1.0f);
    am[n0 + 1] = fminf(fmaxf(wsumB, 0.0f), 1.0f);
    if (n0 == 0) out[0] = 0.0f;
}

// ---------------- K2: composite, warp-shared fp16 weights ----------------
__global__ void __launch_bounds__(K2_THREADS, 5)
rn_composite(const float* __restrict__ feat,
             float* __restrict__ out)
{
    const int wid0 = (blockIdx.x * K2_THREADS + threadIdx.x) >> 5;
    const int lane = threadIdx.x & 31;
    const int c2   = lane >> 3;     // 0..3 channel within group
    const int q8   = lane & 7;      // 0..7 quad within group

    float* rgb = out + 1;
    float* fe  = out + 1 + (size_t)RN_C * RN_N;
    const size_t ZN = (size_t)RN_Z * (size_t)RN_N;

    for (int wj = wid0; wj < K2_WARPJOBS; wj += K2_NWARPS) {
        const int cg = wj >> 11;               // 0..7 channel group
        const int qg = wj & 2047;              // 0..2047 quad group
        const int c  = cg * 4 + c2;            // channel 0..31
        const int n0 = (qg * 8 + q8) * 4;      // ray start

        const float*  fp = feat + (size_t)c * ZN + n0;
        const __half* wp = g_wbuf + n0;

        float4 a = {0.f, 0.f, 0.f, 0.f};
#pragma unroll 4
        for (int z = 0; z < RN_Z; ++z) {
            uint2 wraw = __ldg((const uint2*)(wp + (size_t)z * RN_N));
            const __half2* wh = (const __half2*)&wraw;
            float2 w01 = __half22float2(wh[0]);
            float2 w23 = __half22float2(wh[1]);
            float4 v = __ldcs((const float4*)(fp + (size_t)z * RN_N));
            a.x = fmaf(w01.x, v.x, a.x);
            a.y = fmaf(w01.y, v.y, a.y);
            a.z = fmaf(w23.x, v.z, a.z);
            a.w = fmaf(w23.y, v.w, a.w);
        }

        const size_t o0 = (size_t)c * RN_N + n0;
        float av[4] = {a.x, a.y, a.z, a.w};
#pragma unroll
        for (int j = 0; j < 4; ++j) {
            fe[o0 + j]  = av[j];
            rgb[o0 + j] = 1.0f / (1.0f + expf(-av[j])) - 0.5f;
        }
    }
}

// ---------------- generic fallback (any Z/N) ----------------
__global__ void __launch_bounds__(256)
rendernet_generic(const float* __restrict__ feat,
                  const float* __restrict__ occ,
                  const float* __restrict__ z_dist,
                  const float* __restrict__ noise,
                  float* __restrict__ out,
                  int Z, int N)
{
    extern __shared__ float s_d[];
    int tid = threadIdx.x;
    if (tid < Z)
        s_d[tid] = (tid < Z - 1) ? (z_dist[tid + 1] - z_dist[tid]) : FAR_DIST;
    __syncthreads();

    int n = blockIdx.x * blockDim.x + tid;
    if (n >= N) return;

    float acc[RN_C];
#pragma unroll
    for (int c = 0; c < RN_C; ++c) acc[c] = 0.0f;

    const float* occp   = occ + n;
    const float* noisep = noise + (size_t)n * Z;
    const float* featp  = feat + n;
    const size_t ZN = (size_t)Z * (size_t)N;

    float trans = 1.0f, wsum = 0.0f;
    for (int z = 0; z < Z; ++z) {
        float raw = fmaxf(fmaf(noisep[z], RAW_NOISE_STD, occp[(size_t)z * N]), 0.0f);
        float alpha = 1.0f - expf(-raw * s_d[z]);
        float w = alpha * trans;
        trans *= (1.0f - alpha + 1e-10f);
        wsum += w;
        const float* fz = featp + (size_t)z * N;
#pragma unroll
        for (int c = 0; c < RN_C; ++c)
            acc[c] = fmaf(w, fz[(size_t)c * ZN], acc[c]);
    }
    float* rgb = out + 1;
    float* fe  = out + 1 + (size_t)RN_C * N;
    float* am  = out + 1 + 2 * (size_t)RN_C * N;
#pragma unroll
    for (int c = 0; c < RN_C; ++c) {
        float f = acc[c];
        fe[(size_t)c * N + n]  = f;
        rgb[(size_t)c * N + n] = 1.0f / (1.0f + expf(-f)) - 0.5f;
    }
    am[n] = fminf(fmaxf(wsum, 0.0f), 1.0f);
    if (n == 0) out[0] = 0.0f;
}

extern "C" void kernel_launch(void* const* d_in, const int* in_sizes, int n_in,
                              void* d_out, int out_size)
{
    const float* feat   = (const float*)d_in[0];
    const float* occ    = (const float*)d_in[1];
    const float* z_dist = (const float*)d_in[2];
    const float* noise  = (const float*)d_in[3];
    float* out = (float*)d_out;

    int Z = in_sizes[2];
    int N = in_sizes[1] / Z;

    if (Z == RN_Z && N == RN_N) {
        rn_weights<<<RN_N / 128, 64>>>(occ, z_dist, noise, out);
        rn_composite<<<K2_GRID, K2_THREADS>>>(feat, out);
    } else {
        int block = 256;
        int grid = (N + block - 1) / block;
        rendernet_generic<<<grid, block, Z * sizeof(float)>>>(feat, occ, z_dist, noise, out, Z, N);
    }
}